// round 8
// baseline (speedup 1.0000x reference)
#include <cuda_runtime.h>

#define HID   512
#define BATCH 256
#define TLEN  1024
#define GRID  128
#define NTHR  512
#define UNITS 4          // hidden units per block per layer (128*4 = 512)
#define PF    8          // prefetch depth

// Persistent device state (padded so the prefetch pipeline can over-read).
__device__ float g_h1[2][HID * BATCH + PF * BATCH];   // [k][b] transposed
__device__ float g_h2[2][HID * BATCH + PF * BATCH];
__device__ float g_xT[TLEN * BATCH];                  // x transposed to [t][b]
__device__ unsigned long long g_epoch;
__device__ unsigned g_cnt;

__device__ __forceinline__ float sigm(float v) {
    return 1.0f / (1.0f + __expf(-v));
}

__device__ __forceinline__ unsigned long long pack2(float lo, float hi) {
    unsigned long long r;
    asm("mov.b64 %0, {%1, %2};" : "=l"(r) : "f"(lo), "f"(hi));
    return r;
}
__device__ __forceinline__ void unpack2(unsigned long long v, float& lo, float& hi) {
    asm("mov.b64 {%0, %1}, %2;" : "=f"(lo), "=f"(hi) : "l"(v));
}
__device__ __forceinline__ unsigned long long fma2(unsigned long long a,
                                                   unsigned long long b,
                                                   unsigned long long c) {
    unsigned long long d;
    asm("fma.rn.f32x2 %0, %1, %2, %3;" : "=l"(d) : "l"(a), "l"(b), "l"(c));
    return d;
}

// Grid-wide barrier: all GRID blocks co-resident (1 block/SM, 128 <= 148 SMs).
__device__ __forceinline__ void grid_bar(unsigned long long& target) {
    __threadfence();          // release
    __syncthreads();
    if (threadIdx.x == 0) {
        target += 1;
        unsigned prev = atomicAdd(&g_cnt, 1u);
        if (prev == GRID - 1) {
            g_cnt = 0;
            __threadfence();
            atomicAdd(&g_epoch, 1ull);
        } else {
            while (*((volatile unsigned long long*)&g_epoch) < target) { }
        }
        __threadfence();      // acquire
    }
    __syncthreads();
}

// 4 packed FMAs: this thread-half's 8 rows (4 row-pairs) for one k.
#define FMA2x4(ACC, HV2, WB)                                         \
    do {                                                             \
        ulonglong2 q0_ = (WB)[0], q1_ = (WB)[1];                     \
        ACC[0] = fma2(q0_.x, (HV2), ACC[0]);                         \
        ACC[1] = fma2(q0_.y, (HV2), ACC[1]);                         \
        ACC[2] = fma2(q1_.x, (HV2), ACC[2]);                         \
        ACC[3] = fma2(q1_.y, (HV2), ACC[3]);                         \
    } while (0)

// Pipelined 512-k GEMV pass, h stream prefetched one PF-body ahead.
// HP = h base (+b applied by caller), WSH = weight smem base already offset
// by this half's 8 rows (16 floats per k stride).
#define GEMV512_PIPE(ACC, HP, WSH, B_)                                \
    do {                                                              \
        float hbuf_[PF];                                              \
        _Pragma("unroll")                                             \
        for (int j_ = 0; j_ < PF; j_++)                               \
            hbuf_[j_] = (HP)[j_ * BATCH + (B_)];                      \
        for (int k0_ = 0; k0_ < HID; k0_ += PF) {                     \
            float hnext_[PF];                                         \
            _Pragma("unroll")                                         \
            for (int j_ = 0; j_ < PF; j_++)                           \
                hnext_[j_] = (HP)[(k0_ + PF + j_) * BATCH + (B_)];    \
            _Pragma("unroll")                                         \
            for (int j_ = 0; j_ < PF; j_++) {                         \
                unsigned long long hv2_ = pack2(hbuf_[j_], hbuf_[j_]);\
                const ulonglong2* wb_ =                               \
                    (const ulonglong2*)((WSH) + ((k0_ + j_) << 4));   \
                FMA2x4(ACC, hv2_, wb_);                               \
            }                                                         \
            _Pragma("unroll")                                         \
            for (int j_ = 0; j_ < PF; j_++) hbuf_[j_] = hnext_[j_];   \
        }                                                             \
    } while (0)

__global__ __launch_bounds__(NTHR, 1)
void lstm_persist(const float* __restrict__ x,
                  const float* __restrict__ W_ih1,
                  const float* __restrict__ W_hh1,
                  const float* __restrict__ b1,
                  const float* __restrict__ W_ih2,
                  const float* __restrict__ W_hh2,
                  const float* __restrict__ b2,
                  const float* __restrict__ W_lin,
                  const float* __restrict__ b_lin,
                  float* __restrict__ out)
{
    extern __shared__ float smem[];
    // smem layout (floats), 16B aligned (same as R5):
    float* W1s   = smem;                 // [512][16]  k-major, slot r = 4*u+gate
    float* W2s   = W1s + HID * 16;       // [1024][16] (k<512: W_ih2, k>=512: W_hh2)
    float* Wih1s = W2s + 2 * HID * 16;   // [16]
    float* b1s   = Wih1s + 16;           // [16]
    float* b2s   = b1s + 16;             // [16]
    float* Wlins = b2s + 16;             // [512]
    float* red   = Wlins + HID;          // [16] warp partials (pad 32)

    const int tid  = threadIdx.x;
    const int bk   = blockIdx.x;
    const int half = tid >> 8;           // 0: rows 0-7 (units 0-1), 1: rows 8-15
    const int b    = tid & 255;          // batch column
    const int base_u = bk * UNITS;

    unsigned long long bar_target = 0;
    if (tid == 0) bar_target = *((volatile unsigned long long*)&g_epoch);

    // ---- load this block's weight slice into shared memory ----
    // local row r = 4*u + gate; global row = gate*HID + (base_u + u)
    for (int idx = tid; idx < HID * 16; idx += NTHR) {
        int k = idx >> 4, r = idx & 15;
        int row = (r & 3) * HID + (base_u + (r >> 2));
        W1s[idx] = W_hh1[row * HID + k];
    }
    for (int idx = tid; idx < 2 * HID * 16; idx += NTHR) {
        int k = idx >> 4, r = idx & 15;
        int row = (r & 3) * HID + (base_u + (r >> 2));
        W2s[idx] = (k < HID) ? W_ih2[row * HID + k]
                             : W_hh2[row * HID + (k - HID)];
    }
    if (tid < 16) {
        int r = tid;
        int row = (r & 3) * HID + (base_u + (r >> 2));
        Wih1s[r] = W_ih1[row];
        b1s[r]   = b1[row];
        b2s[r]   = b2[row];
    }
    for (int idx = tid; idx < HID; idx += NTHR) Wlins[idx] = W_lin[idx];
    const float blin = b_lin[0];

    // ---- prologue: zero initial state (incl. padding), transpose x ----
    {
        const int gsz = GRID * NTHR;
        for (int idx = bk * NTHR + tid; idx < TLEN * BATCH; idx += gsz) {
            int bb = idx >> 10;          // /TLEN
            int tt = idx & (TLEN - 1);
            g_xT[tt * BATCH + bb] = x[idx];
        }
        for (int idx = bk * NTHR + tid; idx < (HID + PF) * BATCH; idx += gsz) {
            g_h1[0][idx] = 0.0f; g_h1[1][idx] = 0.0f;
            g_h2[0][idx] = 0.0f; g_h2[1][idx] = 0.0f;
        }
    }
    grid_bar(bar_target);

    // this thread owns units (2*half, 2*half+1) for batch b
    float c1[2] = {0.0f, 0.0f};
    float c2[2] = {0.0f, 0.0f};

    // 4 packed accumulators: acc[2u+0]=(i,f), acc[2u+1]=(g,o) of local unit u
    unsigned long long acc[4];

    const unsigned long long* Wih1p =
        (const unsigned long long*)Wih1s + 4 * half;
    const unsigned long long* b1p =
        (const unsigned long long*)b1s + 4 * half;
    const unsigned long long* b2p =
        (const unsigned long long*)b2s + 4 * half;
    float* W1h = W1s + 8 * half;
    float* W2h = W2s + 8 * half;

    for (int t = 0; t < TLEN; t++) {
        const int par = t & 1;
        const float* __restrict__ h1p = g_h1[par];
        float*       __restrict__ h1n = g_h1[par ^ 1];
        const float* __restrict__ h2p = g_h2[par];
        float*       __restrict__ h2n = g_h2[par ^ 1];

        // ---------- phase A: layer-1 gates + cell update ----------
        {
            const float xv = g_xT[t * BATCH + b];
            const unsigned long long xv2 = pack2(xv, xv);
#pragma unroll
            for (int j = 0; j < 4; j++) acc[j] = fma2(Wih1p[j], xv2, b1p[j]);

            GEMV512_PIPE(acc, h1p, W1h, b);

#pragma unroll
            for (int u = 0; u < 2; u++) {
                float pi, pf, pg, po;
                unpack2(acc[2 * u + 0], pi, pf);
                unpack2(acc[2 * u + 1], pg, po);
                float c = sigm(pf) * c1[u] + sigm(pi) * tanhf(pg);
                c1[u] = c;
                h1n[(base_u + 2 * half + u) * BATCH + b] = sigm(po) * tanhf(c);
            }
        }

        grid_bar(bar_target);   // the only grid barrier per step

        // ---------- output for step t-1 (reads h2 produced by phase B(t-1)) ----
        if (t > 0) {
            const int bb = bk * 2 + half;
            float s = Wlins[b]       * h2p[b * BATCH + bb]
                    + Wlins[b + 256] * h2p[(b + 256) * BATCH + bb];
#pragma unroll
            for (int o = 16; o > 0; o >>= 1)
                s += __shfl_xor_sync(0xffffffffu, s, o);
            if ((tid & 31) == 0) red[tid >> 5] = s;   // 16 warp partials
            __syncthreads();
            if (b == 0) {
                float r = 0.0f;
#pragma unroll
                for (int w = 0; w < 8; w++) r += red[half * 8 + w];
                out[bb * TLEN + (t - 1)] = r + blin;
            }
        }

        // ---------- phase B: layer-2 gates + cell update ----------
        {
#pragma unroll
            for (int j = 0; j < 4; j++) acc[j] = b2p[j];

            GEMV512_PIPE(acc, h1n, W2h, b);                // input = h1 (new)
            GEMV512_PIPE(acc, h2p, (W2h + HID * 16), b);   // recurrent = h2 (prev)

#pragma unroll
            for (int u = 0; u < 2; u++) {
                float pi, pf, pg, po;
                unpack2(acc[2 * u + 0], pi, pf);
                unpack2(acc[2 * u + 1], pg, po);
                float c = sigm(pf) * c2[u] + sigm(pi) * tanhf(pg);
                c2[u] = c;
                h2n[(base_u + 2 * half + u) * BATCH + b] = sigm(po) * tanhf(c);
            }
        }
    }

    // ---------- final output (t = TLEN-1) ----------
    grid_bar(bar_target);
    {
        const float* __restrict__ h2f = g_h2[0];   // TLEN even: last write buf 0
        const int bb = bk * 2 + half;
        float s = Wlins[b]       * h2f[b * BATCH + bb]
                + Wlins[b + 256] * h2f[(b + 256) * BATCH + bb];
#pragma unroll
        for (int o = 16; o > 0; o >>= 1)
            s += __shfl_xor_sync(0xffffffffu, s, o);
        if ((tid & 31) == 0) red[tid >> 5] = s;
        __syncthreads();
        if (b == 0) {
            float r = 0.0f;
#pragma unroll
            for (int w = 0; w < 8; w++) r += red[half * 8 + w];
            out[bb * TLEN + (TLEN - 1)] = r + blin;
        }
    }
}

extern "C" void kernel_launch(void* const* d_in, const int* in_sizes, int n_in,
                              void* d_out, int out_size)
{
    (void)in_sizes; (void)n_in; (void)out_size;
    const float* x     = (const float*)d_in[0];
    const float* W_ih1 = (const float*)d_in[1];
    const float* W_hh1 = (const float*)d_in[2];
    const float* b1    = (const float*)d_in[3];
    const float* W_ih2 = (const float*)d_in[4];
    const float* W_hh2 = (const float*)d_in[5];
    const float* b2    = (const float*)d_in[6];
    const float* W_lin = (const float*)d_in[7];
    const float* b_lin = (const float*)d_in[8];
    float* out = (float*)d_out;

    const size_t smem_bytes =
        (size_t)(HID * 16 + 2 * HID * 16 + 16 + 16 + 16 + HID + 32) * sizeof(float);

    cudaFuncSetAttribute(lstm_persist,
                         cudaFuncAttributeMaxDynamicSharedMemorySize,
                         (int)smem_bytes);

    lstm_persist<<<GRID, NTHR, smem_bytes>>>(
        x, W_ih1, W_hh1, b1, W_ih2, W_hh2, b2, W_lin, b_lin, out);
}

// round 10
// speedup vs baseline: 2.2082x; 2.2082x over previous
#include <cuda_runtime.h>
#include <cuda_bf16.h>
#include <cstdint>

#define HID   512
#define BATCH 256
#define TLEN  1024
#define GRID  128
#define NTHR  256

// smem byte offsets
#define SM_A      0                      // 96 chunks x 2 mh x 1024B = 196608
#define SM_GATES  196608                 // 32 x 132 fp32 = 16896
#define SM_WIH1   213504                 // 32 fp32
#define SM_B1     213632
#define SM_B2     213760
#define SM_WLIN   213888                 // 512 fp32
#define SM_TOTAL  215936

// B-fragment image: [kc(32)][nbhalf(2)][g(4)][tile(4)][lane(32)][16B]
// 16B = {b0hi(2bf16), b1hi, b0lo, b1lo}; 32 chunks x 16384B = 524288B
__device__ __align__(16) unsigned char g_h1img[2][524288];
__device__ __align__(16) unsigned char g_h2img[2][524288];
__device__ float g_h2f32[2][BATCH * HID];   // [b][u] for the output head
__device__ float g_xT[TLEN * BATCH];        // x transposed [t][b]
__device__ unsigned long long g_epoch;
__device__ unsigned g_cnt;

#define MMA_BF16(D, A0, A1, A2, A3, B0, B1)                                   \
    asm volatile(                                                             \
        "mma.sync.aligned.m16n8k16.row.col.f32.bf16.bf16.f32 "                \
        "{%0,%1,%2,%3}, {%4,%5,%6,%7}, {%8,%9}, {%0,%1,%2,%3};"               \
        : "+f"((D)[0]), "+f"((D)[1]), "+f"((D)[2]), "+f"((D)[3])              \
        : "r"(A0), "r"(A1), "r"(A2), "r"(A3), "r"(B0), "r"(B1))

__device__ __forceinline__ void grid_bar(unsigned long long& target, int tid) {
    __threadfence();
    __syncthreads();
    if (tid == 0) {
        target += 1;
        unsigned prev = atomicAdd(&g_cnt, 1u);
        if (prev == GRID - 1) {
            g_cnt = 0;
            __threadfence();
            atomicAdd(&g_epoch, 1ull);
        } else {
            while (*((volatile unsigned long long*)&g_epoch) < target) { }
        }
        __threadfence();
    }
    __syncthreads();
}

// One GEMM range: nch k16-chunks, A resident in smem (fragment-packed),
// B LDG.128'd from a fragment image. Chunk-pair software pipeline.
__device__ __forceinline__ void gemm_range(const char* asmb, const char* bimg,
                                           int nch, float d[4][4]) {
    uint4 B[8], Bn[8];
#pragma unroll
    for (int t = 0; t < 4; t++) {
        B[t]     = *(const uint4*)(bimg + 0 * 16384 + t * 512);
        B[4 + t] = *(const uint4*)(bimg + 1 * 16384 + t * 512);
    }
    for (int c = 0; c < nch; c += 2) {
        if (c + 2 < nch) {
#pragma unroll
            for (int t = 0; t < 4; t++) {
                Bn[t]     = *(const uint4*)(bimg + (c + 2) * 16384 + t * 512);
                Bn[4 + t] = *(const uint4*)(bimg + (c + 3) * 16384 + t * 512);
            }
        }
#pragma unroll
        for (int h = 0; h < 2; h++) {
            uint4 Ah = *(const uint4*)(asmb + (c + h) * 2048);
            uint4 Al = *(const uint4*)(asmb + (c + h) * 2048 + 512);
#pragma unroll
            for (int t = 0; t < 4; t++) {
                uint4 Bv = B[h * 4 + t];
                MMA_BF16(d[t], Ah.x, Ah.y, Ah.z, Ah.w, Bv.x, Bv.y);  // hi*hi
                MMA_BF16(d[t], Ah.x, Ah.y, Ah.z, Ah.w, Bv.z, Bv.w);  // hi*lo
                MMA_BF16(d[t], Al.x, Al.y, Al.z, Al.w, Bv.x, Bv.y);  // lo*hi
            }
        }
        if (c + 2 < nch) {
#pragma unroll
            for (int i = 0; i < 8; i++) B[i] = Bn[i];
        }
    }
}

__global__ __launch_bounds__(NTHR, 1)
void lstm_mma(const float* __restrict__ x, const float* __restrict__ W_ih1,
              const float* __restrict__ W_hh1, const float* __restrict__ b1,
              const float* __restrict__ W_ih2, const float* __restrict__ W_hh2,
              const float* __restrict__ b2, const float* __restrict__ W_lin,
              const float* __restrict__ b_lin, float* __restrict__ out)
{
    extern __shared__ char smch[];
    const int tid = threadIdx.x, wid = tid >> 5, lane = tid & 31;
    const int bk = blockIdx.x;
    const int rt = bk >> 1;          // row-tile 0..63 (units rt*8 .. rt*8+7)
    const int nb = bk & 1;           // batch half
    const int mh = wid >> 2;         // warp m-half (m16 tile)
    const int g  = wid & 3;          // warp n-group (n32)

    unsigned long long bar_target = 0;
    if (tid == 0) bar_target = *((volatile unsigned long long*)&g_epoch);

    float* gsm  = (float*)(smch + SM_GATES);
    float* wih1 = (float*)(smch + SM_WIH1);
    float* b1s  = (float*)(smch + SM_B1);
    float* b2s  = (float*)(smch + SM_B2);
    float* wl   = (float*)(smch + SM_WLIN);

    // ---- block-local init: biases / wih1 by local row r, wlin ----
    // local row r in [0,32): grow(r) = (r&3)*HID + rt*8 + (r>>2)
    if (tid < 32) {
        int grow = (tid & 3) * HID + rt * 8 + (tid >> 2);
        wih1[tid] = W_ih1[grow];
        b1s[tid]  = b1[grow];
        b2s[tid]  = b2[grow];
    }
    for (int i = tid; i < HID; i += NTHR) wl[i] = W_lin[i];
    const float blin = b_lin[0];

    // ---- A pack: 96 chunks x 2 mh x 32 lane x 4 regs, hi/lo bf16 ----
    for (int idx = tid; idx < 96 * 2 * 32 * 4; idx += NTHR) {
        int j = idx & 3, l = (idx >> 2) & 31, mhp = (idx >> 7) & 1, c = idx >> 8;
        int m16row = (j & 1) * 8 + (l >> 2);
        int r = mhp * 16 + m16row;
        int grow = (r & 3) * HID + rt * 8 + (r >> 2);
        int kk0 = ((j >> 1) & 1) * 8 + 2 * (l & 3);
        float w0, w1;
        if (c < 32) {
            int kg = c * 16 + kk0;
            w0 = W_hh1[grow * HID + kg]; w1 = W_hh1[grow * HID + kg + 1];
        } else {
            int kl = (c - 32) * 16 + kk0;
            if (kl < HID) { w0 = W_ih2[grow * HID + kl]; w1 = W_ih2[grow * HID + kl + 1]; }
            else { w0 = W_hh2[grow * HID + kl - HID]; w1 = W_hh2[grow * HID + kl - HID + 1]; }
        }
        __nv_bfloat16 h0 = __float2bfloat16(w0), h1v = __float2bfloat16(w1);
        __nv_bfloat16 l0 = __float2bfloat16(w0 - __bfloat162float(h0));
        __nv_bfloat16 l1 = __float2bfloat16(w1 - __bfloat162float(h1v));
        uint32_t hp = ((uint32_t)*(uint16_t*)&h1v << 16) | *(uint16_t*)&h0;
        uint32_t lp = ((uint32_t)*(uint16_t*)&l1  << 16) | *(uint16_t*)&l0;
        char* base = smch + SM_A + c * 2048 + mhp * 1024 + l * 16 + j * 4;
        *(uint32_t*)base = hp;
        *(uint32_t*)(base + 512) = lp;
    }

    // ---- global prologue: zero step-0 images, transpose x ----
    {
        const int gt = bk * NTHR + tid, gs = GRID * NTHR;
        unsigned long long* z1 = (unsigned long long*)g_h1img[0];
        unsigned long long* z2 = (unsigned long long*)g_h2img[0];
        for (int i = gt; i < 524288 / 8; i += gs) { z1[i] = 0ull; z2[i] = 0ull; }
        for (int i = gt; i < TLEN * BATCH; i += gs)
            g_xT[(i & (TLEN - 1)) * BATCH + (i >> 10)] = x[i];
    }
    grid_bar(bar_target, tid);

    // per-thread activation partition: unit u_l = tid>>5, batches (tid&31)*4 + e
    float c1r[4] = {0.f, 0.f, 0.f, 0.f};
    float c2r[4] = {0.f, 0.f, 0.f, 0.f};
    const int u_l = tid >> 5, bl0 = (tid & 31) * 4;
    const int rbase = (u_l >> 2) * 16 + 4 * (u_l & 3);
    const int ug = rt * 8 + u_l;
    const int kcw = ug >> 4, kk = ug & 15, kk7 = kk & 7;
    const size_t woffW = (size_t)kcw * 16384 + ((kk < 8) ? 0 : 4) + (kk & 1) * 2;

    const size_t woff = (size_t)(nb * 4 + g) * 2048 + lane * 16;
    const char* asmA = smch + SM_A + mh * 1024 + lane * 16;

    float d[4][4];

    for (int t = 0; t < TLEN; t++) {
        const int pr = t & 1, pw = pr ^ 1;

        // ---- output head y(t-1): reads h2f32[pr] (written at t-1) ----
        if (t > 0 && wid < 2) {
            int b = 2 * bk + wid;
            const float* hb = g_h2f32[pr] + b * HID;
            float s = 0.f;
#pragma unroll
            for (int i = 0; i < 16; i++) s += wl[lane + 32 * i] * hb[lane + 32 * i];
#pragma unroll
            for (int o = 16; o > 0; o >>= 1) s += __shfl_xor_sync(~0u, s, o);
            if (lane == 0) out[b * TLEN + t - 1] = s + blin;
        }

        // ================= phase A: layer-1 gates =================
#pragma unroll
        for (int i = 0; i < 16; i++) d[i >> 2][i & 3] = 0.f;
        gemm_range(asmA, (const char*)g_h1img[pr] + woff, 32, d);

        {   // store fragments to gates smem
            int r0 = mh * 16 + (lane >> 2), r1 = r0 + 8;
            int cb = g * 32 + 2 * (lane & 3);
#pragma unroll
            for (int tl = 0; tl < 4; tl++) {
                *(float2*)&gsm[r0 * 132 + cb + tl * 8] = make_float2(d[tl][0], d[tl][1]);
                *(float2*)&gsm[r1 * 132 + cb + tl * 8] = make_float2(d[tl][2], d[tl][3]);
            }
        }
        __syncthreads();
        {   // layer-1 activation
            unsigned char* img = g_h1img[pw];
#pragma unroll
            for (int e = 0; e < 4; e++) {
                int bl = bl0 + e, bg = nb * 128 + bl;
                float xv = g_xT[t * BATCH + bg];
                float gi = gsm[(rbase + 0) * 132 + bl] + b1s[rbase + 0] + wih1[rbase + 0] * xv;
                float gf = gsm[(rbase + 1) * 132 + bl] + b1s[rbase + 1] + wih1[rbase + 1] * xv;
                float gg = gsm[(rbase + 2) * 132 + bl] + b1s[rbase + 2] + wih1[rbase + 2] * xv;
                float go = gsm[(rbase + 3) * 132 + bl] + b1s[rbase + 3] + wih1[rbase + 3] * xv;
                float i_ = 1.f / (1.f + __expf(-gi));
                float f_ = 1.f / (1.f + __expf(-gf));
                float o_ = 1.f / (1.f + __expf(-go));
                float c = f_ * c1r[e] + i_ * tanhf(gg);
                c1r[e] = c;
                float hv = o_ * tanhf(c);
                __nv_bfloat16 hh = __float2bfloat16(hv);
                __nv_bfloat16 hl = __float2bfloat16(hv - __bfloat162float(hh));
                int c32 = bl & 31, tile = c32 >> 3, col8 = c32 & 7;
                int ln = col8 * 4 + (kk7 >> 1);
                size_t off = woffW + (size_t)(nb * 4 + (bl >> 5)) * 2048 + tile * 512 + ln * 16;
                *(__nv_bfloat16*)(img + off) = hh;
                *(__nv_bfloat16*)(img + off + 8) = hl;
            }
        }
        grid_bar(bar_target, tid);

        // ================= phase B: layer-2 gates =================
#pragma unroll
        for (int i = 0; i < 16; i++) d[i >> 2][i & 3] = 0.f;
        gemm_range(asmA + 32 * 2048, (const char*)g_h1img[pw] + woff, 32, d);
        gemm_range(asmA + 64 * 2048, (const char*)g_h2img[pr] + woff, 32, d);

        {
            int r0 = mh * 16 + (lane >> 2), r1 = r0 + 8;
            int cb = g * 32 + 2 * (lane & 3);
#pragma unroll
            for (int tl = 0; tl < 4; tl++) {
                *(float2*)&gsm[r0 * 132 + cb + tl * 8] = make_float2(d[tl][0], d[tl][1]);
                *(float2*)&gsm[r1 * 132 + cb + tl * 8] = make_float2(d[tl][2], d[tl][3]);
            }
        }
        __syncthreads();
        {   // layer-2 activation
            unsigned char* img = g_h2img[pw];
            float* h2o = g_h2f32[pw];
#pragma unroll
            for (int e = 0; e < 4; e++) {
                int bl = bl0 + e, bg = nb * 128 + bl;
                float gi = gsm[(rbase + 0) * 132 + bl] + b2s[rbase + 0];
                float gf = gsm[(rbase + 1) * 132 + bl] + b2s[rbase + 1];
                float gg = gsm[(rbase + 2) * 132 + bl] + b2s[rbase + 2];
                float go = gsm[(rbase + 3) * 132 + bl] + b2s[rbase + 3];
                float i_ = 1.f / (1.f + __expf(-gi));
                float f_ = 1.f / (1.f + __expf(-gf));
                float o_ = 1.f / (1.f + __expf(-go));
                float c = f_ * c2r[e] + i_ * tanhf(gg);
                c2r[e] = c;
                float hv = o_ * tanhf(c);
                __nv_bfloat16 hh = __float2bfloat16(hv);
                __nv_bfloat16 hl = __float2bfloat16(hv - __bfloat162float(hh));
                int c32 = bl & 31, tile = c32 >> 3, col8 = c32 & 7;
                int ln = col8 * 4 + (kk7 >> 1);
                size_t off = woffW + (size_t)(nb * 4 + (bl >> 5)) * 2048 + tile * 512 + ln * 16;
                *(__nv_bfloat16*)(img + off) = hh;
                *(__nv_bfloat16*)(img + off + 8) = hl;
                h2o[bg * HID + ug] = hv;
            }
        }
        grid_bar(bar_target, tid);
    }

    // ---- final output y(T-1): h2f32[(TLEN)&1 == 0] ----
    if (wid < 2) {
        int b = 2 * bk + wid;
        const float* hb = g_h2f32[0] + b * HID;
        float s = 0.f;
#pragma unroll
        for (int i = 0; i < 16; i++) s += wl[lane + 32 * i] * hb[lane + 32 * i];
#pragma unroll
        for (int o = 16; o > 0; o >>= 1) s += __shfl_xor_sync(~0u, s, o);
        if (lane == 0) out[b * TLEN + TLEN - 1] = s + blin;
    }
}

extern "C" void kernel_launch(void* const* d_in, const int* in_sizes, int n_in,
                              void* d_out, int out_size)
{
    (void)in_sizes; (void)n_in; (void)out_size;
    cudaFuncSetAttribute(lstm_mma, cudaFuncAttributeMaxDynamicSharedMemorySize,
                         SM_TOTAL);
    lstm_mma<<<GRID, NTHR, SM_TOTAL>>>(
        (const float*)d_in[0], (const float*)d_in[1], (const float*)d_in[2],
        (const float*)d_in[3], (const float*)d_in[4], (const float*)d_in[5],
        (const float*)d_in[6], (const float*)d_in[7], (const float*)d_in[8],
        (float*)d_out);
}

// round 11
// speedup vs baseline: 3.4570x; 1.5656x over previous
#include <cuda_runtime.h>
#include <cuda_bf16.h>
#include <cstdint>

#define HID   512
#define BATCH 256
#define TLEN  1024
#define GRID  128
#define NTHR  256

// smem byte offsets
#define SM_A      0                      // 96 chunks x 2 mh x 1024B = 196608
#define SM_GATES  196608                 // 32 x 132 fp32 = 16896
#define SM_WIH1   213504                 // 32 fp32
#define SM_B1     213632
#define SM_B2     213760
#define SM_WLIN   213888                 // 512 fp32
#define SM_TOTAL  215936

// B-fragment image: [kc(32)][nb(2)][flat_tile(16)][lane(32)][16B]
// 16B = {b0hi,b1hi,b0lo,b1lo}; 32 chunks x 16384B = 524288B
__device__ __align__(16) unsigned char g_h1img[2][524288];
__device__ __align__(16) unsigned char g_h2img[2][524288];
__device__ float g_h2f32[2][BATCH * HID];   // [b][u] for the output head
__device__ float g_xT[TLEN * BATCH];        // x transposed [t][b]
__device__ unsigned long long g_epoch;
__device__ unsigned g_cnt;

#define MMA_BF16(D, A0, A1, A2, A3, B0, B1)                                   \
    asm volatile(                                                             \
        "mma.sync.aligned.m16n8k16.row.col.f32.bf16.bf16.f32 "                \
        "{%0,%1,%2,%3}, {%4,%5,%6,%7}, {%8,%9}, {%0,%1,%2,%3};"               \
        : "+f"((D)[0]), "+f"((D)[1]), "+f"((D)[2]), "+f"((D)[3])              \
        : "r"(A0), "r"(A1), "r"(A2), "r"(A3), "r"(B0), "r"(B1))

__device__ __forceinline__ void grid_bar(unsigned long long& target, int tid) {
    __threadfence();
    __syncthreads();
    if (tid == 0) {
        target += 1;
        unsigned prev = atomicAdd(&g_cnt, 1u);
        if (prev == GRID - 1) {
            g_cnt = 0;
            __threadfence();
            atomicAdd(&g_epoch, 1ull);
        } else {
            while (*((volatile unsigned long long*)&g_epoch) < target) { }
        }
        __threadfence();
    }
    __syncthreads();
}

// load one quad (4 chunks x 2 tiles) of B fragments; bimg pre-offset by
// nb*8192 + wid*1024 + lane*16
__device__ __forceinline__ void loadq(uint4 B[8], const char* bimg, int q) {
#pragma unroll
    for (int j = 0; j < 8; j++)
        B[j] = *(const uint4*)(bimg + (q * 4 + (j >> 1)) * 16384 + (j & 1) * 512);
}

// compute one quad: 4 chunks x (2 mh x 2 tiles x 3 MMAs)
// a0 = A smem (mh0) pre-offset by range + lane*16; a1 = a0 + 1024
__device__ __forceinline__ void compq(float d[4][4], const char* a0, const char* a1,
                                      int cbase, const uint4 B[8]) {
#pragma unroll
    for (int cl = 0; cl < 4; cl++) {
        int co = (cbase + cl) * 2048;
        uint4 Ah0 = *(const uint4*)(a0 + co);
        uint4 Al0 = *(const uint4*)(a0 + co + 512);
        uint4 Ah1 = *(const uint4*)(a1 + co);
        uint4 Al1 = *(const uint4*)(a1 + co + 512);
#pragma unroll
        for (int t = 0; t < 2; t++) {
            uint4 Bv = B[cl * 2 + t];
            MMA_BF16(d[0 + t], Ah0.x, Ah0.y, Ah0.z, Ah0.w, Bv.x, Bv.y);  // hi*hi
            MMA_BF16(d[0 + t], Ah0.x, Ah0.y, Ah0.z, Ah0.w, Bv.z, Bv.w);  // hi*lo
            MMA_BF16(d[0 + t], Al0.x, Al0.y, Al0.z, Al0.w, Bv.x, Bv.y);  // lo*hi
            MMA_BF16(d[2 + t], Ah1.x, Ah1.y, Ah1.z, Ah1.w, Bv.x, Bv.y);
            MMA_BF16(d[2 + t], Ah1.x, Ah1.y, Ah1.z, Ah1.w, Bv.z, Bv.w);
            MMA_BF16(d[2 + t], Al1.x, Al1.y, Al1.z, Al1.w, Bv.x, Bv.y);
        }
    }
}

// 32-chunk GEMM range with quad-level double buffering
__device__ __forceinline__ void gemm32(float d[4][4], const char* a0, const char* a1,
                                       const char* bimg) {
    uint4 Ba[8], Bb[8];
    loadq(Ba, bimg, 0);
#pragma unroll
    for (int q = 0; q < 8; q += 2) {
        loadq(Bb, bimg, q + 1);
        compq(d, a0, a1, q * 4, Ba);
        if (q + 2 < 8) loadq(Ba, bimg, q + 2);
        compq(d, a0, a1, (q + 1) * 4, Bb);
    }
}

__global__ __launch_bounds__(NTHR, 1)
void lstm_mma(const float* __restrict__ x, const float* __restrict__ W_ih1,
              const float* __restrict__ W_hh1, const float* __restrict__ b1,
              const float* __restrict__ W_ih2, const float* __restrict__ W_hh2,
              const float* __restrict__ b2, const float* __restrict__ W_lin,
              const float* __restrict__ b_lin, float* __restrict__ out)
{
    extern __shared__ char smch[];
    const int tid = threadIdx.x, wid = tid >> 5, lane = tid & 31;
    const int bk = blockIdx.x;
    const int rt = bk >> 1;          // row-tile 0..63 (units rt*8 .. rt*8+7)
    const int nb = bk & 1;           // batch half

    unsigned long long bar_target = 0;
    if (tid == 0) bar_target = *((volatile unsigned long long*)&g_epoch);

    float* gsm  = (float*)(smch + SM_GATES);
    float* wih1 = (float*)(smch + SM_WIH1);
    float* b1s  = (float*)(smch + SM_B1);
    float* b2s  = (float*)(smch + SM_B2);
    float* wl   = (float*)(smch + SM_WLIN);

    if (tid < 32) {
        int grow = (tid & 3) * HID + rt * 8 + (tid >> 2);
        wih1[tid] = W_ih1[grow];
        b1s[tid]  = b1[grow];
        b2s[tid]  = b2[grow];
    }
    for (int i = tid; i < HID; i += NTHR) wl[i] = W_lin[i];
    const float blin = b_lin[0];

    // ---- A pack: 96 chunks x 2 mh x 32 lane x 4 regs, hi/lo bf16 ----
    for (int idx = tid; idx < 96 * 2 * 32 * 4; idx += NTHR) {
        int j = idx & 3, l = (idx >> 2) & 31, mhp = (idx >> 7) & 1, c = idx >> 8;
        int m16row = (j & 1) * 8 + (l >> 2);
        int r = mhp * 16 + m16row;
        int grow = (r & 3) * HID + rt * 8 + (r >> 2);
        int kk0 = ((j >> 1) & 1) * 8 + 2 * (l & 3);
        float w0, w1;
        if (c < 32) {
            int kg = c * 16 + kk0;
            w0 = W_hh1[grow * HID + kg]; w1 = W_hh1[grow * HID + kg + 1];
        } else {
            int kl = (c - 32) * 16 + kk0;
            if (kl < HID) { w0 = W_ih2[grow * HID + kl]; w1 = W_ih2[grow * HID + kl + 1]; }
            else { w0 = W_hh2[grow * HID + kl - HID]; w1 = W_hh2[grow * HID + kl - HID + 1]; }
        }
        __nv_bfloat16 h0 = __float2bfloat16(w0), h1v = __float2bfloat16(w1);
        __nv_bfloat16 l0 = __float2bfloat16(w0 - __bfloat162float(h0));
        __nv_bfloat16 l1 = __float2bfloat16(w1 - __bfloat162float(h1v));
        uint32_t hp = ((uint32_t)*(uint16_t*)&h1v << 16) | *(uint16_t*)&h0;
        uint32_t lp = ((uint32_t)*(uint16_t*)&l1  << 16) | *(uint16_t*)&l0;
        char* base = smch + SM_A + c * 2048 + mhp * 1024 + l * 16 + j * 4;
        *(uint32_t*)base = hp;
        *(uint32_t*)(base + 512) = lp;
    }

    // ---- global prologue ----
    {
        const int gt = bk * NTHR + tid, gs = GRID * NTHR;
        unsigned long long* z1 = (unsigned long long*)g_h1img[0];
        unsigned long long* z2 = (unsigned long long*)g_h2img[0];
        for (int i = gt; i < 524288 / 8; i += gs) { z1[i] = 0ull; z2[i] = 0ull; }
        for (int i = gt; i < TLEN * BATCH; i += gs)
            g_xT[(i & (TLEN - 1)) * BATCH + (i >> 10)] = x[i];
    }
    grid_bar(bar_target, tid);

    // activation partition: unit u_l = tid>>5, batches (tid&31)*4 + e
    float c1r[4] = {0.f, 0.f, 0.f, 0.f};
    float c2r[4] = {0.f, 0.f, 0.f, 0.f};
    const int u_l = tid >> 5, bl0 = (tid & 31) * 4;
    const int rbase = (u_l >> 2) * 16 + 4 * (u_l & 3);
    const int ug = rt * 8 + u_l;
    const int kcw = ug >> 4, kk = ug & 15, kk7 = kk & 7;
    const size_t woffW = (size_t)kcw * 16384 + ((kk < 8) ? 0 : 4) + (kk & 1) * 2;

    // per-warp B base: disjoint n16 slice (flat tiles wid*2, wid*2+1)
    const size_t woff = (size_t)nb * 8192 + (size_t)wid * 1024 + lane * 16;
    const char* a0 = smch + SM_A + lane * 16;       // mh0
    const char* a1 = a0 + 1024;                     // mh1

    float d[4][4];

    for (int t = 0; t < TLEN; t++) {
        const int pr = t & 1, pw = pr ^ 1;

        // ================= phase A: layer-1 gates =================
#pragma unroll
        for (int i = 0; i < 16; i++) d[i >> 2][i & 3] = 0.f;
        gemm32(d, a0, a1, (const char*)g_h1img[pr] + woff);

        {   // fragments -> gates smem (warp owns cols [wid*16, wid*16+16))
            int cb = wid * 16 + 2 * (lane & 3);
            int rr = lane >> 2;
#pragma unroll
            for (int mhp = 0; mhp < 2; mhp++)
#pragma unroll
                for (int tl = 0; tl < 2; tl++) {
                    float* dd = d[mhp * 2 + tl];
                    *(float2*)&gsm[(mhp * 16 + rr) * 132 + cb + tl * 8] =
                        make_float2(dd[0], dd[1]);
                    *(float2*)&gsm[(mhp * 16 + rr + 8) * 132 + cb + tl * 8] =
                        make_float2(dd[2], dd[3]);
                }
        }
        __syncthreads();
        {   // layer-1 activation
            unsigned char* img = g_h1img[pw];
#pragma unroll
            for (int e = 0; e < 4; e++) {
                int bl = bl0 + e, bg = nb * 128 + bl;
                float xv = g_xT[t * BATCH + bg];
                float gi = gsm[(rbase + 0) * 132 + bl] + b1s[rbase + 0] + wih1[rbase + 0] * xv;
                float gf = gsm[(rbase + 1) * 132 + bl] + b1s[rbase + 1] + wih1[rbase + 1] * xv;
                float gg = gsm[(rbase + 2) * 132 + bl] + b1s[rbase + 2] + wih1[rbase + 2] * xv;
                float go = gsm[(rbase + 3) * 132 + bl] + b1s[rbase + 3] + wih1[rbase + 3] * xv;
                float i_ = 1.f / (1.f + __expf(-gi));
                float f_ = 1.f / (1.f + __expf(-gf));
                float o_ = 1.f / (1.f + __expf(-go));
                float c = f_ * c1r[e] + i_ * tanhf(gg);
                c1r[e] = c;
                float hv = o_ * tanhf(c);
                __nv_bfloat16 hh = __float2bfloat16(hv);
                __nv_bfloat16 hl = __float2bfloat16(hv - __bfloat162float(hh));
                int c32 = bl & 31, tile = c32 >> 3, col8 = c32 & 7;
                int ln = col8 * 4 + (kk7 >> 1);
                size_t off = woffW + (size_t)(nb * 4 + (bl >> 5)) * 2048 + tile * 512 + ln * 16;
                *(__nv_bfloat16*)(img + off) = hh;
                *(__nv_bfloat16*)(img + off + 8) = hl;
            }
        }

        grid_bar(bar_target, tid);   // the ONLY grid barrier per step

        // ---- output head y(t-1): h2f32[pr] was written at B(t-1) ----
        if (t > 0 && wid < 2) {
            int b = 2 * bk + wid;
            const float* hb = g_h2f32[pr] + b * HID;
            float s = 0.f;
#pragma unroll
            for (int i = 0; i < 16; i++) s += wl[lane + 32 * i] * hb[lane + 32 * i];
#pragma unroll
            for (int o = 16; o > 0; o >>= 1) s += __shfl_xor_sync(~0u, s, o);
            if (lane == 0) out[b * TLEN + t - 1] = s + blin;
        }

        // ================= phase B: layer-2 gates =================
#pragma unroll
        for (int i = 0; i < 16; i++) d[i >> 2][i & 3] = 0.f;
        gemm32(d, a0 + 32 * 2048, a1 + 32 * 2048, (const char*)g_h1img[pw] + woff);
        gemm32(d, a0 + 64 * 2048, a1 + 64 * 2048, (const char*)g_h2img[pr] + woff);

        {
            int cb = wid * 16 + 2 * (lane & 3);
            int rr = lane >> 2;
#pragma unroll
            for (int mhp = 0; mhp < 2; mhp++)
#pragma unroll
                for (int tl = 0; tl < 2; tl++) {
                    float* dd = d[mhp * 2 + tl];
                    *(float2*)&gsm[(mhp * 16 + rr) * 132 + cb + tl * 8] =
                        make_float2(dd[0], dd[1]);
                    *(float2*)&gsm[(mhp * 16 + rr + 8) * 132 + cb + tl * 8] =
                        make_float2(dd[2], dd[3]);
                }
        }
        __syncthreads();
        {   // layer-2 activation
            unsigned char* img = g_h2img[pw];
            float* h2o = g_h2f32[pw];
#pragma unroll
            for (int e = 0; e < 4; e++) {
                int bl = bl0 + e, bg = nb * 128 + bl;
                float gi = gsm[(rbase + 0) * 132 + bl] + b2s[rbase + 0];
                float gf = gsm[(rbase + 1) * 132 + bl] + b2s[rbase + 1];
                float gg = gsm[(rbase + 2) * 132 + bl] + b2s[rbase + 2];
                float go = gsm[(rbase + 3) * 132 + bl] + b2s[rbase + 3];
                float i_ = 1.f / (1.f + __expf(-gi));
                float f_ = 1.f / (1.f + __expf(-gf));
                float o_ = 1.f / (1.f + __expf(-go));
                float c = f_ * c2r[e] + i_ * tanhf(gg);
                c2r[e] = c;
                float hv = o_ * tanhf(c);
                __nv_bfloat16 hh = __float2bfloat16(hv);
                __nv_bfloat16 hl = __float2bfloat16(hv - __bfloat162float(hh));
                int c32 = bl & 31, tile = c32 >> 3, col8 = c32 & 7;
                int ln = col8 * 4 + (kk7 >> 1);
                size_t off = woffW + (size_t)(nb * 4 + (bl >> 5)) * 2048 + tile * 512 + ln * 16;
                *(__nv_bfloat16*)(img + off) = hh;
                *(__nv_bfloat16*)(img + off + 8) = hl;
                h2o[bg * HID + ug] = hv;
            }
        }
        __syncthreads();   // protect gates smem vs next step's stores
    }

    // ---- final output y(T-1) ----
    grid_bar(bar_target, tid);
    if (wid < 2) {
        int b = 2 * bk + wid;
        const float* hb = g_h2f32[0] + b * HID;
        float s = 0.f;
#pragma unroll
        for (int i = 0; i < 16; i++) s += wl[lane + 32 * i] * hb[lane + 32 * i];
#pragma unroll
        for (int o = 16; o > 0; o >>= 1) s += __shfl_xor_sync(~0u, s, o);
        if (lane == 0) out[b * TLEN + TLEN - 1] = s + blin;
    }
}

extern "C" void kernel_launch(void* const* d_in, const int* in_sizes, int n_in,
                              void* d_out, int out_size)
{
    (void)in_sizes; (void)n_in; (void)out_size;
    cudaFuncSetAttribute(lstm_mma, cudaFuncAttributeMaxDynamicSharedMemorySize,
                         SM_TOTAL);
    lstm_mma<<<GRID, NTHR, SM_TOTAL>>>(
        (const float*)d_in[0], (const float*)d_in[1], (const float*)d_in[2],
        (const float*)d_in[3], (const float*)d_in[4], (const float*)d_in[5],
        (const float*)d_in[6], (const float*)d_in[7], (const float*)d_in[8],
        (float*)d_out);
}